// round 6
// baseline (speedup 1.0000x reference)
#include <cuda_runtime.h>
#include <cuda_fp16.h>
#include <math.h>

#define CTAS     128
#define NTHREADS 256
#define TSTEPS   512
#define NBATCH   64
#define HID      1024
#define EMB      512

// ---------------- device scratch (static, no allocation) ----------------
__device__ __half g_X16[(size_t)TSTEPS * NBATCH * EMB];             // 32 MB
__device__ __half g_xproj[(size_t)TSTEPS * CTAS * NBATCH * 32];     // 256 MB
__device__ __half g_hbuf[2][NBATCH * HID];                          // double-buffered h
__device__ volatile unsigned g_flags[CTAS];                         // per-CTA step flags

struct Params {
    const float* Wx[4];   // i,f,g,o : [EMB][HID]
    const float* Wh[4];   // i,f,g,o : [HID][HID]
    const float* b[4];    // i,f,g,o : [HID]
    float* out;           // [T][B][HID]
};

// ---------------- smem layout (bytes) ----------------
// Phase B layout:
#define OFF_WF     0                      // Wh B-fragments (64 KB)
#define SZ_WF      65536
#define OFF_GATES  (OFF_WF + SZ_WF)       // [64][34] fp32
#define SZ_GATES   (64 * 34 * 4)
#define OFF_XP     (OFF_GATES + SZ_GATES) // [64][32] fp16
#define SZ_XP      4096
#define OFF_PAD    (OFF_XP + SZ_XP)       // 128 (alignment)
#define OFF_ABUF   (OFF_PAD + 128)        // A tile: 64 rows x 1032 halves
#define SZ_ABUF    (64 * 1032 * 2)
#define SMEM_TOTAL (OFF_ABUF + SZ_ABUF)   // 210560 bytes
#define A_STRIDE   1032                   // halves/row: 2064 B, == 16 mod 128 -> conflict-free ldmatrix

// Phase A overlay layout (same dynamic smem):
//   Wx frags:  [0, 32768)
//   gatesA:    [32768, 41472)
//   abufA0:    [41472, 108032)   64 rows x 520 halves (1040 B/row, == 16 mod 128)
//   abufA1:    [108032, 174592)
#define OFFA_GATES 32768
#define OFFA_BUF0  41472
#define OFFA_BUF1  108032
#define A_STRIDE_A 520

// ---------------- PTX helpers ----------------
__device__ __forceinline__ unsigned su32(const void* p) {
    return (unsigned)__cvta_generic_to_shared(p);
}
__device__ __forceinline__ void cp16(unsigned s, const void* g) {
    asm volatile("cp.async.cg.shared.global [%0], [%1], 16;\n" :: "r"(s), "l"(g));
}
__device__ __forceinline__ void cp_commit() { asm volatile("cp.async.commit_group;\n"); }
template<int N> __device__ __forceinline__ void cp_wait() {
    asm volatile("cp.async.wait_group %0;\n" :: "n"(N));
}
__device__ __forceinline__ void ldmx4(unsigned r[4], unsigned addr) {
    asm volatile("ldmatrix.sync.aligned.m8n8.x4.shared.b16 {%0,%1,%2,%3}, [%4];\n"
                 : "=r"(r[0]), "=r"(r[1]), "=r"(r[2]), "=r"(r[3]) : "r"(addr));
}
__device__ __forceinline__ void hmma(float acc[4], const unsigned a[4], unsigned b0, unsigned b1) {
    asm volatile("mma.sync.aligned.m16n8k16.row.col.f32.f16.f16.f32 "
                 "{%0,%1,%2,%3},{%4,%5,%6,%7},{%8,%9},{%0,%1,%2,%3};\n"
                 : "+f"(acc[0]), "+f"(acc[1]), "+f"(acc[2]), "+f"(acc[3])
                 : "r"(a[0]), "r"(a[1]), "r"(a[2]), "r"(a[3]), "r"(b0), "r"(b1));
}
__device__ __forceinline__ float sigf(float x) { return 1.0f / (1.0f + expf(-x)); }

// Pre-pack W[k][n] (fp32, stride HID) into per-lane mma B-fragments (fp16) in SMEM.
__device__ void prep_frags(uint2* dst, int nk, const float* const W[4], int hid0, int tid) {
    int total = 4 * nk * 32;
    for (int e = tid; e < total; e += NTHREADS) {
        int L  = e & 31;
        int ks = (e >> 5) % nk;
        int g  = e / (nk * 32);
        int t4 = L & 3, gid = L >> 2;
        const float* Wg = W[g];
        int k0 = ks * 16 + 2 * t4;
        int n  = hid0 + gid;
        __half2 lo = __floats2half2_rn(Wg[(k0    ) * HID + n], Wg[(k0 + 1) * HID + n]);
        __half2 hi = __floats2half2_rn(Wg[(k0 + 8) * HID + n], Wg[(k0 + 9) * HID + n]);
        unsigned ulo = *reinterpret_cast<unsigned*>(&lo);
        unsigned uhi = *reinterpret_cast<unsigned*>(&hi);
        dst[e] = make_uint2(ulo, uhi);
    }
}

// Run CNT k-steps of mma for this warp's 2 gate tiles.
template<int CNT>
__device__ __forceinline__ void mma_run(float acc[2][4], unsigned a_lane,
                                        const uint2* b0p, const uint2* b1p, int ks0) {
#pragma unroll
    for (int i = 0; i < CNT; i++) {
        int ks = ks0 + i;
        unsigned a[4];
        ldmx4(a, a_lane + (unsigned)ks * 32u);   // 16 halves = 32 B per kstep
        uint2 q0 = b0p[ks * 32];
        uint2 q1 = b1p[ks * 32];
        hmma(acc[0], a, q0.x, q0.y);
        hmma(acc[1], a, q1.x, q1.y);
    }
}

// Flag-array grid barrier: no atomic contention, pure spin (no nanosleep —
// its wakeup quantum added ~µs per step in R5).
// Only warp 0 polls (4 flags/lane); other warps wait at the closing bar.
__device__ __forceinline__ void grid_barrier(unsigned target, int cta, int tid) {
    __threadfence();            // make this thread's global writes GPU-visible
    __syncthreads();            // all threads of this CTA fenced
    if (tid == 0) g_flags[cta] = target;
    if (tid < 32) {
        bool done = false;
        while (!done) {
            done = true;
#pragma unroll
            for (int q = 0; q < CTAS / 32; q++) {
                if (g_flags[tid + q * 32] < target) done = false;
            }
        }
    }
    __syncthreads();
    __threadfence();            // acquire: order peer data reads after flag observation
}

// ---------------- setup / convert kernels ----------------
__global__ void setup_kernel() {
    int tid = threadIdx.x;
    if (tid < CTAS) g_flags[tid] = 0;
    uint4* p = reinterpret_cast<uint4*>(g_hbuf);
    for (int i = tid; i < (2 * NBATCH * HID * 2) / 16; i += NTHREADS)
        p[i] = make_uint4(0, 0, 0, 0);
}

__global__ void convX_kernel(const float* __restrict__ in) {
    int i = blockIdx.x * blockDim.x + threadIdx.x;   // handles 4 floats
    float4 v = reinterpret_cast<const float4*>(in)[i];
    __half2 a = __floats2half2_rn(v.x, v.y);
    __half2 b = __floats2half2_rn(v.z, v.w);
    reinterpret_cast<uint2*>(g_X16)[i] =
        make_uint2(*reinterpret_cast<unsigned*>(&a), *reinterpret_cast<unsigned*>(&b));
}

// ---------------- persistent LSTM kernel ----------------
__global__ void __launch_bounds__(NTHREADS, 1) lstm_kernel(Params P) {
    extern __shared__ char smem[];
    uint2* wfrag   = reinterpret_cast<uint2*>(smem + OFF_WF);
    float* gatesB  = reinterpret_cast<float*>(smem + OFF_GATES);
    __half* xp     = reinterpret_cast<__half*>(smem + OFF_XP);
    float* gatesA  = reinterpret_cast<float*>(smem + OFFA_GATES);

    const int cta  = blockIdx.x;
    const int tid  = threadIdx.x;
    const int w    = tid >> 5;
    const int L    = tid & 31;
    const int hid0 = cta * 8;

    const unsigned smem_u32 = su32(smem);
    const unsigned abufB_u32 = smem_u32 + OFF_ABUF;
    const unsigned xp_u32    = smem_u32 + OFF_XP;

    // warp tiling: m-tile = w&3 (16 batch rows), gate-pair = w>>2 ({i,f} or {g,o})
    const int m0 = (w & 3) * 16;
    const int gp = (w >> 2) * 2;
    const unsigned lane_off = (unsigned)(m0 + ((L >> 3) & 1) * 8 + (L & 7));
    const unsigned lane_col = (unsigned)((L >> 4) * 8);
    const unsigned a_laneB  = abufB_u32 + (lane_off * A_STRIDE   + lane_col) * 2;
    const unsigned a_laneA0 = smem_u32 + OFFA_BUF0 + (lane_off * A_STRIDE_A + lane_col) * 2;
    const unsigned a_laneA1 = smem_u32 + OFFA_BUF1 + (lane_off * A_STRIDE_A + lane_col) * 2;

    const int a_row = tid >> 2, a_cg = tid & 3;

    // Phase A biases in registers: cols a_cg*8+i, gate = a_cg
    float breg[8];
    {
        const float* bp = P.b[a_cg];
#pragma unroll
        for (int i = 0; i < 8; i++) breg[i] = bp[hid0 + i];
    }

    // ================= PHASE A: input projection (double-buffered) =================
    prep_frags(wfrag, 32, P.Wx, hid0, tid);
    __syncthreads();

    const uint2* xb0 = wfrag + (size_t)(gp    ) * 32 * 32 + L;
    const uint2* xb1 = wfrag + (size_t)(gp + 1) * 32 * 32 + L;

    // X tile: 64 rows x 512 halves (1024 B/row = 64 chunks) -> 4096 chunks, 16/thread
    auto loadA = [&](int t, int buf) {
        unsigned base = smem_u32 + (buf ? OFFA_BUF1 : OFFA_BUF0);
#pragma unroll
        for (int jj = 0; jj < 16; jj++) {
            int c = tid + jj * NTHREADS;
            int row = c >> 6, col = c & 63;
            cp16(base + row * (A_STRIDE_A * 2) + col * 16,
                 (const char*)g_X16 + ((size_t)(t * 64 + row) * EMB) * 2 + col * 16);
        }
        cp_commit();
    };

    loadA(0, 0);
    for (int t = 0; t < TSTEPS; t++) {
        if (t + 1 < TSTEPS) { loadA(t + 1, (t + 1) & 1); cp_wait<1>(); }
        else                { cp_wait<0>(); }
        __syncthreads();   // tile t ready; also guards gatesA reuse from prev iter

        float acc[2][4] = {{0,0,0,0},{0,0,0,0}};
        mma_run<32>(acc, (t & 1) ? a_laneA1 : a_laneA0, xb0, xb1, 0);

        // fragments -> gatesA smem
        {
            int gid = L >> 2, t4 = L & 3;
#pragma unroll
            for (int s = 0; s < 2; s++) {
                int colb = (gp + s) * 8 + 2 * t4;
                *reinterpret_cast<float2*>(&gatesA[(m0 + gid    ) * 34 + colb]) = make_float2(acc[s][0], acc[s][1]);
                *reinterpret_cast<float2*>(&gatesA[(m0 + gid + 8) * 34 + colb]) = make_float2(acc[s][2], acc[s][3]);
            }
        }
        __syncthreads();

        // bias add, fp16 pack, store to g_xproj[t][cta][b][32]
        {
            float v[8];
#pragma unroll
            for (int i = 0; i < 8; i++)
                v[i] = gatesA[a_row * 34 + a_cg * 8 + i] + breg[i];
            __half2 h0 = __floats2half2_rn(v[0], v[1]);
            __half2 h1 = __floats2half2_rn(v[2], v[3]);
            __half2 h2 = __floats2half2_rn(v[4], v[5]);
            __half2 h3 = __floats2half2_rn(v[6], v[7]);
            uint4 pk = make_uint4(*reinterpret_cast<unsigned*>(&h0), *reinterpret_cast<unsigned*>(&h1),
                                  *reinterpret_cast<unsigned*>(&h2), *reinterpret_cast<unsigned*>(&h3));
            size_t off = (((size_t)t * CTAS + cta) * NBATCH + a_row) * 32 + a_cg * 8;
            *reinterpret_cast<uint4*>(&g_xproj[off]) = pk;
        }
        // next iter's gatesA write is behind the top cp_wait+sync
    }

    // ================= PHASE B: recurrence =================
    __syncthreads();
    prep_frags(wfrag, 64, P.Wh, hid0, tid);
    __syncthreads();

    const uint2* hb0 = wfrag + (size_t)(gp    ) * 64 * 32 + L;
    const uint2* hb1 = wfrag + (size_t)(gp + 1) * 64 * 32 + L;

    float creg[2] = {0.0f, 0.0f};
    const int e_base = tid * 2;
    const int e_row  = e_base >> 3;
    const int e_j    = e_base & 7;

    for (int t = 0; t < TSTEPS; t++) {
        const __half* hsrc = g_hbuf[t & 1];

        // issue h load in 4 K-quarter groups
        // (each quarter: 64 rows x 32 chunks of 16 B = 2048 chunks -> 8 per thread)
#pragma unroll
        for (int kq = 0; kq < 4; kq++) {
#pragma unroll
            for (int jj = 0; jj < 8; jj++) {
                int c = tid + jj * NTHREADS;
                int row = c >> 5;
                int col = (kq << 5) + (c & 31);
                cp16(abufB_u32 + row * (A_STRIDE * 2) + col * 16,
                     (const char*)hsrc + row * (HID * 2) + col * 16);
            }
            cp_commit();
        }
        // xproj tile (group 5): 4096 B, one 16B chunk per thread
        cp16(xp_u32 + tid * 16,
             (const char*)&g_xproj[(((size_t)t * CTAS + cta) * NBATCH) * 32] + tid * 16);
        cp_commit();

        float acc[2][4] = {{0,0,0,0},{0,0,0,0}};
        cp_wait<4>(); __syncthreads(); mma_run<16>(acc, a_laneB, hb0, hb1, 0);
        cp_wait<3>(); __syncthreads(); mma_run<16>(acc, a_laneB, hb0, hb1, 16);
        cp_wait<2>(); __syncthreads(); mma_run<16>(acc, a_laneB, hb0, hb1, 32);
        cp_wait<1>(); __syncthreads(); mma_run<16>(acc, a_laneB, hb0, hb1, 48);

        // fragments -> gatesB smem
        {
            int gid = L >> 2, t4 = L & 3;
#pragma unroll
            for (int s = 0; s < 2; s++) {
                int colb = (gp + s) * 8 + 2 * t4;
                *reinterpret_cast<float2*>(&gatesB[(m0 + gid    ) * 34 + colb]) = make_float2(acc[s][0], acc[s][1]);
                *reinterpret_cast<float2*>(&gatesB[(m0 + gid + 8) * 34 + colb]) = make_float2(acc[s][2], acc[s][3]);
            }
        }
        cp_wait<0>();
        __syncthreads();

        // elementwise LSTM cell: this thread owns (row=e_row, j=e_j) and (e_row, e_j+1)
        __half* hdst = g_hbuf[(t + 1) & 1];
#pragma unroll
        for (int u = 0; u < 2; u++) {
            int jj = e_j + u;
            float zi = gatesB[e_row * 34 +       jj] + __half2float(xp[e_row * 32 +       jj]);
            float zf = gatesB[e_row * 34 +  8 +  jj] + __half2float(xp[e_row * 32 +  8 +  jj]);
            float zg = gatesB[e_row * 34 + 16 +  jj] + __half2float(xp[e_row * 32 + 16 +  jj]);
            float zo = gatesB[e_row * 34 + 24 +  jj] + __half2float(xp[e_row * 32 + 24 +  jj]);
            float it = sigf(zi);
            float ft = sigf(zf);
            float gt = tanhf(zg);
            float ot = sigf(zo);
            float cn = gt * it + creg[u] * ft;
            creg[u] = cn;
            float hn = tanhf(cn) * ot;
            hdst[e_row * HID + hid0 + jj] = __float2half(hn);
            P.out[((size_t)(t * NBATCH + e_row)) * HID + hid0 + jj] = hn;
        }

        grid_barrier((unsigned)(t + 1), cta, tid);
    }
}

// ---------------- launcher ----------------
extern "C" void kernel_launch(void* const* d_in, const int* in_sizes, int n_in,
                              void* d_out, int out_size) {
    (void)in_sizes; (void)n_in; (void)out_size;
    Params P;
    // metadata order: embeds, W_ix, W_ih, b_i, W_fx, W_fh, b_f, W_gx, W_gh, b_g, W_ox, W_oh, b_o
    const float* embeds = (const float*)d_in[0];
    P.Wx[0] = (const float*)d_in[1];  P.Wh[0] = (const float*)d_in[2];  P.b[0] = (const float*)d_in[3];
    P.Wx[1] = (const float*)d_in[4];  P.Wh[1] = (const float*)d_in[5];  P.b[1] = (const float*)d_in[6];
    P.Wx[2] = (const float*)d_in[7];  P.Wh[2] = (const float*)d_in[8];  P.b[2] = (const float*)d_in[9];
    P.Wx[3] = (const float*)d_in[10]; P.Wh[3] = (const float*)d_in[11]; P.b[3] = (const float*)d_in[12];
    P.out = (float*)d_out;

    cudaFuncSetAttribute(lstm_kernel, cudaFuncAttributeMaxDynamicSharedMemorySize, SMEM_TOTAL);

    setup_kernel<<<1, NTHREADS>>>();
    convX_kernel<<<(TSTEPS * NBATCH * EMB) / 4 / NTHREADS, NTHREADS>>>(embeds);
    lstm_kernel<<<CTAS, NTHREADS, SMEM_TOTAL>>>(P);
}

// round 9
// speedup vs baseline: 1.6295x; 1.6295x over previous
#include <cuda_runtime.h>
#include <cuda_fp16.h>
#include <math.h>

#define CTAS     128
#define NTHREADS 256
#define TSTEPS   512
#define NBATCH   64
#define HID      1024
#define EMB      512

// ---------------- device scratch (static, no allocation) ----------------
__device__ __half g_X16[(size_t)TSTEPS * NBATCH * EMB];             // 32 MB
__device__ __half g_xproj[(size_t)TSTEPS * CTAS * NBATCH * 32];     // 256 MB
__device__ __half g_hbuf[2][NBATCH * HID];                          // double-buffered h
__device__ unsigned g_arrive[CTAS * 32];                            // padded: 1 flag per 128B line

struct Params {
    const float* Wx[4];   // i,f,g,o : [EMB][HID]
    const float* Wh[4];   // i,f,g,o : [HID][HID]
    const float* b[4];    // i,f,g,o : [HID]
    float* out;           // [T][B][HID]
};

// ---------------- smem layout (bytes) ----------------
// Phase B layout:
#define OFF_WF     0                      // Wh B-fragments (64 KB)
#define SZ_WF      65536
#define OFF_GATES  (OFF_WF + SZ_WF)       // [64][34] fp32
#define SZ_GATES   (64 * 34 * 4)
#define OFF_XP     (OFF_GATES + SZ_GATES) // [64][32] fp16
#define SZ_XP      4096
#define OFF_PAD    (OFF_XP + SZ_XP)       // 128 (alignment)
#define OFF_ABUF   (OFF_PAD + 128)        // A tile: 64 rows x 1032 halves
#define SZ_ABUF    (64 * 1032 * 2)
#define SMEM_TOTAL (OFF_ABUF + SZ_ABUF)   // 210560 bytes
#define A_STRIDE   1032                   // halves/row: 2064 B, == 16 mod 128 -> conflict-free ldmatrix

// Phase A overlay layout (same dynamic smem):
#define OFFA_GATES 32768
#define OFFA_BUF0  41472
#define OFFA_BUF1  108032
#define A_STRIDE_A 520

// ---------------- PTX helpers ----------------
__device__ __forceinline__ unsigned su32(const void* p) {
    return (unsigned)__cvta_generic_to_shared(p);
}
__device__ __forceinline__ void cp16(unsigned s, const void* g) {
    asm volatile("cp.async.cg.shared.global [%0], [%1], 16;\n" :: "r"(s), "l"(g));
}
__device__ __forceinline__ void cp_commit() { asm volatile("cp.async.commit_group;\n"); }
template<int N> __device__ __forceinline__ void cp_wait() {
    asm volatile("cp.async.wait_group %0;\n" :: "n"(N));
}
__device__ __forceinline__ void ldmx4(unsigned r[4], unsigned addr) {
    asm volatile("ldmatrix.sync.aligned.m8n8.x4.shared.b16 {%0,%1,%2,%3}, [%4];\n"
                 : "=r"(r[0]), "=r"(r[1]), "=r"(r[2]), "=r"(r[3]) : "r"(addr));
}
__device__ __forceinline__ void hmma(float acc[4], const unsigned a[4], unsigned b0, unsigned b1) {
    asm volatile("mma.sync.aligned.m16n8k16.row.col.f32.f16.f16.f32 "
                 "{%0,%1,%2,%3},{%4,%5,%6,%7},{%8,%9},{%0,%1,%2,%3};\n"
                 : "+f"(acc[0]), "+f"(acc[1]), "+f"(acc[2]), "+f"(acc[3])
                 : "r"(a[0]), "r"(a[1]), "r"(a[2]), "r"(a[3]), "r"(b0), "r"(b1));
}
__device__ __forceinline__ float sigf(float x) { return 1.0f / (1.0f + expf(-x)); }

__device__ __forceinline__ unsigned ld_acq(const unsigned* p) {
    unsigned v;
    asm volatile("ld.acquire.gpu.u32 %0, [%1];" : "=r"(v) : "l"(p));
    return v;
}
__device__ __forceinline__ void st_rel(unsigned* p, unsigned v) {
    asm volatile("st.release.gpu.u32 [%0], %1;" :: "l"(p), "r"(v));
}

// Pre-pack W[k][n] (fp32, stride HID) into per-lane mma B-fragments (fp16) in SMEM.
__device__ void prep_frags(uint2* dst, int nk, const float* const W[4], int hid0, int tid) {
    int total = 4 * nk * 32;
    for (int e = tid; e < total; e += NTHREADS) {
        int L  = e & 31;
        int ks = (e >> 5) % nk;
        int g  = e / (nk * 32);
        int t4 = L & 3, gid = L >> 2;
        const float* Wg = W[g];
        int k0 = ks * 16 + 2 * t4;
        int n  = hid0 + gid;
        __half2 lo = __floats2half2_rn(Wg[(k0    ) * HID + n], Wg[(k0 + 1) * HID + n]);
        __half2 hi = __floats2half2_rn(Wg[(k0 + 8) * HID + n], Wg[(k0 + 9) * HID + n]);
        unsigned ulo = *reinterpret_cast<unsigned*>(&lo);
        unsigned uhi = *reinterpret_cast<unsigned*>(&hi);
        dst[e] = make_uint2(ulo, uhi);
    }
}

// Run CNT k-steps of mma for this warp's 2 gate tiles.
template<int CNT>
__device__ __forceinline__ void mma_run(float acc[2][4], unsigned a_lane,
                                        const uint2* b0p, const uint2* b1p, int ks0) {
#pragma unroll
    for (int i = 0; i < CNT; i++) {
        int ks = ks0 + i;
        unsigned a[4];
        ldmx4(a, a_lane + (unsigned)ks * 32u);   // 16 halves = 32 B per kstep
        uint2 q0 = b0p[ks * 32];
        uint2 q1 = b1p[ks * 32];
        hmma(acc[0], a, q0.x, q0.y);
        hmma(acc[1], a, q1.x, q1.y);
    }
}

// ---------------- setup / convert kernels ----------------
__global__ void setup_kernel() {
    int tid = threadIdx.x;
    for (int i = tid; i < CTAS * 32; i += NTHREADS) g_arrive[i] = 0;
    uint4* p = reinterpret_cast<uint4*>(g_hbuf);
    for (int i = tid; i < (2 * NBATCH * HID * 2) / 16; i += NTHREADS)
        p[i] = make_uint4(0, 0, 0, 0);
}

__global__ void convX_kernel(const float* __restrict__ in) {
    int i = blockIdx.x * blockDim.x + threadIdx.x;   // handles 4 floats
    float4 v = reinterpret_cast<const float4*>(in)[i];
    __half2 a = __floats2half2_rn(v.x, v.y);
    __half2 b = __floats2half2_rn(v.z, v.w);
    reinterpret_cast<uint2*>(g_X16)[i] =
        make_uint2(*reinterpret_cast<unsigned*>(&a), *reinterpret_cast<unsigned*>(&b));
}

// ---------------- persistent LSTM kernel ----------------
__global__ void __launch_bounds__(NTHREADS, 1) lstm_kernel(Params P) {
    extern __shared__ char smem[];
    uint2* wfrag   = reinterpret_cast<uint2*>(smem + OFF_WF);
    float* gatesB  = reinterpret_cast<float*>(smem + OFF_GATES);
    __half* xp     = reinterpret_cast<__half*>(smem + OFF_XP);
    float* gatesA  = reinterpret_cast<float*>(smem + OFFA_GATES);

    const int cta  = blockIdx.x;
    const int tid  = threadIdx.x;
    const int w    = tid >> 5;
    const int L    = tid & 31;
    const int hid0 = cta * 8;

    const unsigned smem_u32 = su32(smem);
    const unsigned abufB_u32 = smem_u32 + OFF_ABUF;
    const unsigned xp_u32    = smem_u32 + OFF_XP;

    // warp tiling: m-tile = w&3 (16 batch rows), gate-pair = w>>2 ({i,f} or {g,o})
    const int m0 = (w & 3) * 16;
    const int gp = (w >> 2) * 2;
    const unsigned lane_off = (unsigned)(m0 + ((L >> 3) & 1) * 8 + (L & 7));
    const unsigned lane_col = (unsigned)((L >> 4) * 8);
    const unsigned a_laneB  = abufB_u32 + (lane_off * A_STRIDE   + lane_col) * 2;
    const unsigned a_laneA0 = smem_u32 + OFFA_BUF0 + (lane_off * A_STRIDE_A + lane_col) * 2;
    const unsigned a_laneA1 = smem_u32 + OFFA_BUF1 + (lane_off * A_STRIDE_A + lane_col) * 2;

    const int a_row = tid >> 2, a_cg = tid & 3;

    // Phase A biases in registers: cols a_cg*8+i, gate = a_cg
    float breg[8];
    {
        const float* bp = P.b[a_cg];
#pragma unroll
        for (int i = 0; i < 8; i++) breg[i] = bp[hid0 + i];
    }

    // ================= PHASE A: input projection (double-buffered) =================
    prep_frags(wfrag, 32, P.Wx, hid0, tid);
    __syncthreads();

    const uint2* xb0 = wfrag + (size_t)(gp    ) * 32 * 32 + L;
    const uint2* xb1 = wfrag + (size_t)(gp + 1) * 32 * 32 + L;

    // X tile: 64 rows x 512 halves (1024 B/row = 64 chunks) -> 4096 chunks, 16/thread
    auto loadA = [&](int t, int buf) {
        unsigned base = smem_u32 + (buf ? OFFA_BUF1 : OFFA_BUF0);
#pragma unroll
        for (int jj = 0; jj < 16; jj++) {
            int c = tid + jj * NTHREADS;
            int row = c >> 6, col = c & 63;
            cp16(base + row * (A_STRIDE_A * 2) + col * 16,
                 (const char*)g_X16 + ((size_t)(t * 64 + row) * EMB) * 2 + col * 16);
        }
        cp_commit();
    };

    loadA(0, 0);
    for (int t = 0; t < TSTEPS; t++) {
        if (t + 1 < TSTEPS) { loadA(t + 1, (t + 1) & 1); cp_wait<1>(); }
        else                { cp_wait<0>(); }
        __syncthreads();   // tile t ready; also guards gatesA reuse from prev iter

        float acc[2][4] = {{0,0,0,0},{0,0,0,0}};
        mma_run<32>(acc, (t & 1) ? a_laneA1 : a_laneA0, xb0, xb1, 0);

        // fragments -> gatesA smem
        {
            int gid = L >> 2, t4 = L & 3;
#pragma unroll
            for (int s = 0; s < 2; s++) {
                int colb = (gp + s) * 8 + 2 * t4;
                *reinterpret_cast<float2*>(&gatesA[(m0 + gid    ) * 34 + colb]) = make_float2(acc[s][0], acc[s][1]);
                *reinterpret_cast<float2*>(&gatesA[(m0 + gid + 8) * 34 + colb]) = make_float2(acc[s][2], acc[s][3]);
            }
        }
        __syncthreads();

        // bias add, fp16 pack, store to g_xproj[t][cta][b][32]
        {
            float v[8];
#pragma unroll
            for (int i = 0; i < 8; i++)
                v[i] = gatesA[a_row * 34 + a_cg * 8 + i] + breg[i];
            __half2 h0 = __floats2half2_rn(v[0], v[1]);
            __half2 h1 = __floats2half2_rn(v[2], v[3]);
            __half2 h2 = __floats2half2_rn(v[4], v[5]);
            __half2 h3 = __floats2half2_rn(v[6], v[7]);
            uint4 pk = make_uint4(*reinterpret_cast<unsigned*>(&h0), *reinterpret_cast<unsigned*>(&h1),
                                  *reinterpret_cast<unsigned*>(&h2), *reinterpret_cast<unsigned*>(&h3));
            size_t off = (((size_t)t * CTAS + cta) * NBATCH + a_row) * 32 + a_cg * 8;
            *reinterpret_cast<uint4*>(&g_xproj[off]) = pk;
        }
        // next iter's gatesA write is behind the top cp_wait+sync
    }

    // ================= PHASE B: recurrence =================
    __syncthreads();
    prep_frags(wfrag, 64, P.Wh, hid0, tid);
    __syncthreads();

    const uint2* hb0 = wfrag + (size_t)(gp    ) * 64 * 32 + L;
    const uint2* hb1 = wfrag + (size_t)(gp + 1) * 64 * 32 + L;

    float creg[2] = {0.0f, 0.0f};
    const int e_base = tid * 2;
    const int e_row  = e_base >> 3;
    const int e_j    = e_base & 7;

    // prologue: prefetch xproj(0) (own slice, no cross-CTA dep)
    cp16(xp_u32 + tid * 16,
         (const char*)&g_xproj[((size_t)0 * CTAS + cta) * NBATCH * 32] + tid * 16);
    cp_commit();

    for (int t = 0; t < TSTEPS; t++) {
        const __half* hsrc = g_hbuf[t & 1];

        // issue h load in 4 K-quarter groups
        // (each quarter: 64 rows x 32 chunks of 16 B = 2048 chunks -> 8 per thread)
#pragma unroll
        for (int kq = 0; kq < 4; kq++) {
#pragma unroll
            for (int jj = 0; jj < 8; jj++) {
                int c = tid + jj * NTHREADS;
                int row = c >> 5;
                int col = (kq << 5) + (c & 31);
                cp16(abufB_u32 + row * (A_STRIDE * 2) + col * 16,
                     (const char*)hsrc + row * (HID * 2) + col * 16);
            }
            cp_commit();
        }
        // outstanding per thread: {xp(t), h0, h1, h2, h3}

        float acc[2][4] = {{0,0,0,0},{0,0,0,0}};
        cp_wait<3>(); __syncthreads(); mma_run<16>(acc, a_laneB, hb0, hb1, 0);   // xp+h0 done
        cp_wait<2>(); __syncthreads(); mma_run<16>(acc, a_laneB, hb0, hb1, 16);
        cp_wait<1>(); __syncthreads(); mma_run<16>(acc, a_laneB, hb0, hb1, 32);
        cp_wait<0>(); __syncthreads(); mma_run<16>(acc, a_laneB, hb0, hb1, 48);

        // fragments -> gatesB smem
        {
            int gid = L >> 2, t4 = L & 3;
#pragma unroll
            for (int s = 0; s < 2; s++) {
                int colb = (gp + s) * 8 + 2 * t4;
                *reinterpret_cast<float2*>(&gatesB[(m0 + gid    ) * 34 + colb]) = make_float2(acc[s][0], acc[s][1]);
                *reinterpret_cast<float2*>(&gatesB[(m0 + gid + 8) * 34 + colb]) = make_float2(acc[s][2], acc[s][3]);
            }
        }
        __syncthreads();

        // elementwise LSTM cell: this thread owns (row=e_row, j=e_j) and (e_row, e_j+1)
        __half* hdst = g_hbuf[(t + 1) & 1];
#pragma unroll
        for (int u = 0; u < 2; u++) {
            int jj = e_j + u;
            float zi = gatesB[e_row * 34 +       jj] + __half2float(xp[e_row * 32 +       jj]);
            float zf = gatesB[e_row * 34 +  8 +  jj] + __half2float(xp[e_row * 32 +  8 +  jj]);
            float zg = gatesB[e_row * 34 + 16 +  jj] + __half2float(xp[e_row * 32 + 16 +  jj]);
            float zo = gatesB[e_row * 34 + 24 +  jj] + __half2float(xp[e_row * 32 + 24 +  jj]);
            float it = sigf(zi);
            float ft = sigf(zf);
            float gt = tanhf(zg);
            float ot = sigf(zo);
            float cn = gt * it + creg[u] * ft;
            creg[u] = cn;
            float hn = tanhf(cn) * ot;
            hdst[e_row * HID + hid0 + jj] = __float2half(hn);
            P.out[((size_t)(t * NBATCH + e_row)) * HID + hid0 + jj] = hn;
        }

        // ---- padded-flag grid barrier (all CTAs poll; xp(t+1) prefetch in window) ----
        unsigned target = (unsigned)(t + 1);
        __syncthreads();   // all threads' h/out/xp-reads complete
        if (tid == 0) st_rel(&g_arrive[cta * 32], target);
        if (t + 1 < TSTEPS) {   // prefetch next xproj slice; hides behind barrier wait
            cp16(xp_u32 + tid * 16,
                 (const char*)&g_xproj[(((size_t)(t + 1) * CTAS + cta) * NBATCH) * 32] + tid * 16);
            cp_commit();
        }
        if (tid < 32) {
            for (;;) {
                bool done = true;
#pragma unroll
                for (int q = 0; q < CTAS / 32; q++)
                    if (ld_acq(&g_arrive[(tid + q * 32) * 32]) < target) done = false;
                if (done) break;
            }
        }
        __syncthreads();   // acquires in warp 0 + bar order all threads' h reads
    }
}

// ---------------- launcher ----------------
extern "C" void kernel_launch(void* const* d_in, const int* in_sizes, int n_in,
                              void* d_out, int out_size) {
    (void)in_sizes; (void)n_in; (void)out_size;
    Params P;
    // metadata order: embeds, W_ix, W_ih, b_i, W_fx, W_fh, b_f, W_gx, W_gh, b_g, W_ox, W_oh, b_o
    const float* embeds = (const float*)d_in[0];
    P.Wx[0] = (const float*)d_in[1];  P.Wh[0] = (const float*)d_in[2];  P.b[0] = (const float*)d_in[3];
    P.Wx[1] = (const float*)d_in[4];  P.Wh[1] = (const float*)d_in[5];  P.b[1] = (const float*)d_in[6];
    P.Wx[2] = (const float*)d_in[7];  P.Wh[2] = (const float*)d_in[8];  P.b[2] = (const float*)d_in[9];
    P.Wx[3] = (const float*)d_in[10]; P.Wh[3] = (const float*)d_in[11]; P.b[3] = (const float*)d_in[12];
    P.out = (float*)d_out;

    cudaFuncSetAttribute(lstm_kernel, cudaFuncAttributeMaxDynamicSharedMemorySize, SMEM_TOTAL);

    setup_kernel<<<1, NTHREADS>>>();
    convX_kernel<<<(TSTEPS * NBATCH * EMB) / 4 / NTHREADS, NTHREADS>>>(embeds);
    lstm_kernel<<<CTAS, NTHREADS, SMEM_TOTAL>>>(P);
}

// round 11
// speedup vs baseline: 1.8634x; 1.1435x over previous
#include <cuda_runtime.h>
#include <cuda_fp16.h>
#include <math.h>

#define CTAS     128
#define NTHREADS 256
#define TSTEPS   512
#define NBATCH   64
#define HID      1024
#define EMB      512
#define BROWS    32        // batch rows per CTA  (batch split = 2)
#define NC       16        // cols per gate per CTA (hid split = 64)

// ---------------- device scratch (static, no allocation) ----------------
__device__ __half g_X16[(size_t)TSTEPS * NBATCH * EMB];             // 32 MB
__device__ __half g_xproj[(size_t)TSTEPS * CTAS * BROWS * 64];      // 256 MB
__device__ __half g_hbuf[2][NBATCH * HID];                          // double-buffered h
__device__ unsigned g_arrive[CTAS * 32];                            // padded: 1 flag per 128B line

struct Params {
    const float* Wx[4];   // i,f,g,o : [EMB][HID]
    const float* Wh[4];   // i,f,g,o : [HID][HID]
    const float* b[4];    // i,f,g,o : [HID]
    float* out;           // [T][B][HID]
};

// ---------------- smem layout (bytes) ----------------
// Phase B:
#define OFF_WF     0                       // Wh B-frags: 4 gates x 2 colgrp x 64 ks x 32 lanes x 8B
#define SZ_WF      131072
#define OFF_GATES  (OFF_WF + SZ_WF)        // [32][66] fp32
#define SZ_GATES   (32 * 66 * 4)
#define OFF_XP     (OFF_GATES + SZ_GATES)  // [32][64] fp16
#define SZ_XP      4096
#define OFF_ABUF   (OFF_XP + SZ_XP + 128)  // A tile: 32 rows x 1032 halves
#define SZ_ABUF    (32 * 1032 * 2)
#define SMEM_TOTAL (OFF_ABUF + SZ_ABUF)    // ~209.8 KB
#define A_STRIDE   1032                    // 2064 B/row, == 16 mod 128 -> conflict-free ldmatrix

// Phase A overlay:
#define OFFA_GATES 65536                   // Wx frags occupy [0, 65536)
#define OFFA_BUF0  73984                   // 32 x 520 halves
#define OFFA_BUF1  (73984 + 33280)
#define A_STRIDE_A 520

// ---------------- PTX helpers ----------------
__device__ __forceinline__ unsigned su32(const void* p) {
    return (unsigned)__cvta_generic_to_shared(p);
}
__device__ __forceinline__ void cp16(unsigned s, const void* g) {
    asm volatile("cp.async.cg.shared.global [%0], [%1], 16;\n" :: "r"(s), "l"(g));
}
__device__ __forceinline__ void cp_commit() { asm volatile("cp.async.commit_group;\n"); }
template<int N> __device__ __forceinline__ void cp_wait() {
    asm volatile("cp.async.wait_group %0;\n" :: "n"(N));
}
__device__ __forceinline__ void ldmx4(unsigned r[4], unsigned addr) {
    asm volatile("ldmatrix.sync.aligned.m8n8.x4.shared.b16 {%0,%1,%2,%3}, [%4];\n"
                 : "=r"(r[0]), "=r"(r[1]), "=r"(r[2]), "=r"(r[3]) : "r"(addr));
}
__device__ __forceinline__ void hmma(float acc[4], const unsigned a[4], unsigned b0, unsigned b1) {
    asm volatile("mma.sync.aligned.m16n8k16.row.col.f32.f16.f16.f32 "
                 "{%0,%1,%2,%3},{%4,%5,%6,%7},{%8,%9},{%0,%1,%2,%3};\n"
                 : "+f"(acc[0]), "+f"(acc[1]), "+f"(acc[2]), "+f"(acc[3])
                 : "r"(a[0]), "r"(a[1]), "r"(a[2]), "r"(a[3]), "r"(b0), "r"(b1));
}
__device__ __forceinline__ float sigf(float x) { return 1.0f / (1.0f + expf(-x)); }

__device__ __forceinline__ unsigned ld_acq(const unsigned* p) {
    unsigned v;
    asm volatile("ld.acquire.gpu.u32 %0, [%1];" : "=r"(v) : "l"(p));
    return v;
}
__device__ __forceinline__ void st_rel(unsigned* p, unsigned v) {
    asm volatile("st.release.gpu.u32 [%0], %1;" :: "l"(p), "r"(v));
}

// Pre-pack W[k][n] into per-lane mma B-fragments (fp16) in SMEM.
// Unit u = g*2+cg (gate g, col-group cg of 8 cols). Entry index: ((u*nk)+ks)*32 + L.
// Lane L: t4=L&3, gid=L>>2; n = hid0 + cg*8 + gid; k0 = ks*16 + 2*t4.
__device__ void prep_frags(uint2* dst, int nk, const float* const W[4], int hid0, int tid) {
    int total = 8 * nk * 32;
    for (int e = tid; e < total; e += NTHREADS) {
        int L  = e & 31;
        int ks = (e >> 5) % nk;
        int u  = e / (nk * 32);
        int g  = u >> 1, cg = u & 1;
        int t4 = L & 3, gid = L >> 2;
        const float* Wg = W[g];
        int k0 = ks * 16 + 2 * t4;
        int n  = hid0 + cg * 8 + gid;
        __half2 lo = __floats2half2_rn(Wg[(k0    ) * HID + n], Wg[(k0 + 1) * HID + n]);
        __half2 hi = __floats2half2_rn(Wg[(k0 + 8) * HID + n], Wg[(k0 + 9) * HID + n]);
        unsigned ulo = *reinterpret_cast<unsigned*>(&lo);
        unsigned uhi = *reinterpret_cast<unsigned*>(&hi);
        dst[e] = make_uint2(ulo, uhi);
    }
}

// Run CNT k-steps of mma for this warp's 2 col-group tiles (one gate).
template<int CNT>
__device__ __forceinline__ void mma_run(float acc[2][4], unsigned a_lane,
                                        const uint2* b0p, const uint2* b1p, int ks0) {
#pragma unroll
    for (int i = 0; i < CNT; i++) {
        int ks = ks0 + i;
        unsigned a[4];
        ldmx4(a, a_lane + (unsigned)ks * 32u);   // 16 halves = 32 B per kstep
        uint2 q0 = b0p[ks * 32];
        uint2 q1 = b1p[ks * 32];
        hmma(acc[0], a, q0.x, q0.y);
        hmma(acc[1], a, q1.x, q1.y);
    }
}

// ---------------- setup / convert kernels ----------------
__global__ void setup_kernel() {
    int tid = threadIdx.x;
    for (int i = tid; i < CTAS * 32; i += NTHREADS) g_arrive[i] = 0;
    uint4* p = reinterpret_cast<uint4*>(g_hbuf);
    for (int i = tid; i < (2 * NBATCH * HID * 2) / 16; i += NTHREADS)
        p[i] = make_uint4(0, 0, 0, 0);
}

__global__ void convX_kernel(const float* __restrict__ in) {
    int i = blockIdx.x * blockDim.x + threadIdx.x;   // handles 4 floats
    float4 v = reinterpret_cast<const float4*>(in)[i];
    __half2 a = __floats2half2_rn(v.x, v.y);
    __half2 b = __floats2half2_rn(v.z, v.w);
    reinterpret_cast<uint2*>(g_X16)[i] =
        make_uint2(*reinterpret_cast<unsigned*>(&a), *reinterpret_cast<unsigned*>(&b));
}

// ---------------- persistent LSTM kernel ----------------
__global__ void __launch_bounds__(NTHREADS, 1) lstm_kernel(Params P) {
    extern __shared__ char smem[];
    uint2* wfrag   = reinterpret_cast<uint2*>(smem + OFF_WF);
    float* gatesB  = reinterpret_cast<float*>(smem + OFF_GATES);
    __half* xp     = reinterpret_cast<__half*>(smem + OFF_XP);
    float* gatesA  = reinterpret_cast<float*>(smem + OFFA_GATES);

    const int cta  = blockIdx.x;
    const int tid  = threadIdx.x;
    const int w    = tid >> 5;
    const int L    = tid & 31;
    const int hid0 = (cta >> 1) * NC;     // 16 cols/gate
    const int b0   = (cta & 1) * BROWS;   // 32 batch rows

    const unsigned smem_u32 = su32(smem);
    const unsigned abufB_u32 = smem_u32 + OFF_ABUF;
    const unsigned xp_u32    = smem_u32 + OFF_XP;

    // warp tiling: m-tile = w&1 (16 rows), gate = w>>1; warp covers both col-groups of its gate
    const int m0 = (w & 1) * 16;
    const int wg = w >> 1;                // gate 0..3
    const unsigned lane_off = (unsigned)(m0 + ((L >> 3) & 1) * 8 + (L & 7));
    const unsigned lane_col = (unsigned)((L >> 4) * 8);
    const unsigned a_laneB  = abufB_u32 + (lane_off * A_STRIDE   + lane_col) * 2;
    const unsigned a_laneA0 = smem_u32 + OFFA_BUF0 + (lane_off * A_STRIDE_A + lane_col) * 2;
    const unsigned a_laneA1 = smem_u32 + OFFA_BUF1 + (lane_off * A_STRIDE_A + lane_col) * 2;

    // Phase A epilogue mapping: thread -> (row = tid>>3, col-group cg8 = tid&7 of 8 cols in 0..63)
    const int a_row = tid >> 3, a_cg = tid & 7;

    // biases for Phase A epilogue: col64 = a_cg*8 + i -> gate = a_cg>>1, within = (a_cg&1)*8 + i
    float breg[8];
    {
        const float* bp = P.b[a_cg >> 1];
#pragma unroll
        for (int i = 0; i < 8; i++) breg[i] = bp[hid0 + (a_cg & 1) * 8 + i];
    }

    // ================= PHASE A: input projection (double-buffered) =================
    prep_frags(wfrag, 32, P.Wx, hid0, tid);
    __syncthreads();

    const uint2* xb0 = wfrag + (size_t)(wg * 2    ) * 32 * 32 + L;
    const uint2* xb1 = wfrag + (size_t)(wg * 2 + 1) * 32 * 32 + L;

    // X tile: 32 rows x 512 halves (64 chunks/row) -> 2048 chunks, 8/thread
    auto loadA = [&](int t, int buf) {
        unsigned base = smem_u32 + (buf ? OFFA_BUF1 : OFFA_BUF0);
#pragma unroll
        for (int jj = 0; jj < 8; jj++) {
            int c = tid + jj * NTHREADS;
            int row = c >> 6, col = c & 63;
            cp16(base + row * (A_STRIDE_A * 2) + col * 16,
                 (const char*)g_X16 + ((size_t)(t * NBATCH + b0 + row) * EMB) * 2 + col * 16);
        }
        cp_commit();
    };

    loadA(0, 0);
    for (int t = 0; t < TSTEPS; t++) {
        if (t + 1 < TSTEPS) { loadA(t + 1, (t + 1) & 1); cp_wait<1>(); }
        else                { cp_wait<0>(); }
        __syncthreads();   // tile t ready; also guards gatesA reuse from prev iter

        float acc[2][4] = {{0,0,0,0},{0,0,0,0}};
        mma_run<32>(acc, (t & 1) ? a_laneA1 : a_laneA0, xb0, xb1, 0);

        // fragments -> gatesA smem ([32][66], col = gate*16 + cg*8 + 2*t4)
        {
            int gid = L >> 2, t4 = L & 3;
#pragma unroll
            for (int s = 0; s < 2; s++) {
                int colb = wg * 16 + s * 8 + 2 * t4;
                *reinterpret_cast<float2*>(&gatesA[(m0 + gid    ) * 66 + colb]) = make_float2(acc[s][0], acc[s][1]);
                *reinterpret_cast<float2*>(&gatesA[(m0 + gid + 8) * 66 + colb]) = make_float2(acc[s][2], acc[s][3]);
            }
        }
        __syncthreads();

        // bias add, fp16 pack, store to g_xproj[t][cta][row][64]
        {
            float v[8];
#pragma unroll
            for (int i = 0; i < 8; i++)
                v[i] = gatesA[a_row * 66 + a_cg * 8 + i] + breg[i];
            __half2 h0 = __floats2half2_rn(v[0], v[1]);
            __half2 h1 = __floats2half2_rn(v[2], v[3]);
            __half2 h2 = __floats2half2_rn(v[4], v[5]);
            __half2 h3 = __floats2half2_rn(v[6], v[7]);
            uint4 pk = make_uint4(*reinterpret_cast<unsigned*>(&h0), *reinterpret_cast<unsigned*>(&h1),
                                  *reinterpret_cast<unsigned*>(&h2), *reinterpret_cast<unsigned*>(&h3));
            size_t off = (((size_t)t * CTAS + cta) * BROWS + a_row) * 64 + a_cg * 8;
            *reinterpret_cast<uint4*>(&g_xproj[off]) = pk;
        }
        // next iter's gatesA write is behind the top cp_wait+sync
    }

    // ================= PHASE B: recurrence =================
    __syncthreads();
    prep_frags(wfrag, 64, P.Wh, hid0, tid);
    __syncthreads();

    const uint2* hb0 = wfrag + (size_t)(wg * 2    ) * 64 * 32 + L;
    const uint2* hb1 = wfrag + (size_t)(wg * 2 + 1) * 64 * 32 + L;

    float creg[2] = {0.0f, 0.0f};
    const int e_base = tid * 2;
    const int e_row  = e_base >> 4;       // 0..31
    const int e_j    = e_base & 15;       // even col in 0..15

    // prologue: prefetch xproj(0) (own slice, no cross-CTA dep): 4096 B
    cp16(xp_u32 + tid * 16,
         (const char*)&g_xproj[((size_t)0 * CTAS + cta) * BROWS * 64] + tid * 16);
    cp_commit();

    for (int t = 0; t < TSTEPS; t++) {
        const __half* hsrc = g_hbuf[t & 1] + (size_t)b0 * HID;

        // h load: 32 rows x 128 chunks; 4 K-quarter groups of 32 rows x 32 chunks
        // (1024 chunks/quarter -> 4 per thread)
#pragma unroll
        for (int kq = 0; kq < 4; kq++) {
#pragma unroll
            for (int jj = 0; jj < 4; jj++) {
                int c = tid + jj * NTHREADS;
                int row = c >> 5;
                int col = (kq << 5) + (c & 31);
                cp16(abufB_u32 + row * (A_STRIDE * 2) + col * 16,
                     (const char*)hsrc + row * (HID * 2) + col * 16);
            }
            cp_commit();
        }
        // outstanding per thread: {xp(t), h0, h1, h2, h3}

        float acc[2][4] = {{0,0,0,0},{0,0,0,0}};
        cp_wait<3>(); __syncthreads(); mma_run<16>(acc, a_laneB, hb0, hb1, 0);   // xp+h0 done
        cp_wait<2>(); __syncthreads(); mma_run<16>(acc, a_laneB, hb0, hb1, 16);
        cp_wait<1>(); __syncthreads(); mma_run<16>(acc, a_laneB, hb0, hb1, 32);
        cp_wait<0>(); __syncthreads(); mma_run<16>(acc, a_laneB, hb0, hb1, 48);

        // fragments -> gatesB smem
        {
            int gid = L >> 2, t4 = L & 3;
#pragma unroll
            for (int s = 0; s < 2; s++) {
                int colb = wg * 16 + s * 8 + 2 * t4;
                *reinterpret_cast<float2*>(&gatesB[(m0 + gid    ) * 66 + colb]) = make_float2(acc[s][0], acc[s][1]);
                *reinterpret_cast<float2*>(&gatesB[(m0 + gid + 8) * 66 + colb]) = make_float2(acc[s][2], acc[s][3]);
            }
        }
        __syncthreads();

        // elementwise LSTM cell: thread owns (e_row, e_j) and (e_row, e_j+1)
        __half* hdst = g_hbuf[(t + 1) & 1];
#pragma unroll
        for (int u = 0; u < 2; u++) {
            int jj = e_j + u;
            float zi = gatesB[e_row * 66 +       jj] + __half2float(xp[e_row * 64 +       jj]);
            float zf = gatesB[e_row * 66 + 16 +  jj] + __half2float(xp[e_row * 64 + 16 +  jj]);
            float zg = gatesB[e_row * 66 + 32 +  jj] + __half2float(xp[e_row * 64 + 32 +  jj]);
            float zo = gatesB[e_row * 66 + 48 +  jj] + __half2float(xp[e_row * 64 + 48 +  jj]);
            float it = sigf(zi);
            float ft = sigf(zf);
            float gt = tanhf(zg);
            float ot = sigf(zo);
            float cn = gt * it + creg[u] * ft;
            creg[u] = cn;
            float hn = tanhf(cn) * ot;
            hdst[(b0 + e_row) * HID + hid0 + jj] = __float2half(hn);
            P.out[((size_t)(t * NBATCH + b0 + e_row)) * HID + hid0 + jj] = hn;
        }

        // ---- padded-flag grid barrier (all CTAs poll; xp(t+1) prefetch in window) ----
        unsigned target = (unsigned)(t + 1);
        __syncthreads();   // all threads' h/out/xp-reads complete
        if (tid == 0) st_rel(&g_arrive[cta * 32], target);
        if (t + 1 < TSTEPS) {   // prefetch next xproj slice; hides behind barrier wait
            cp16(xp_u32 + tid * 16,
                 (const char*)&g_xproj[(((size_t)(t + 1) * CTAS + cta) * BROWS) * 64] + tid * 16);
            cp_commit();
        }
        if (tid < 32) {
            for (;;) {
                bool done = true;
#pragma unroll
                for (int q = 0; q < CTAS / 32; q++)
                    if (ld_acq(&g_arrive[(tid + q * 32) * 32]) < target) done = false;
                if (done) break;
            }
        }
        __syncthreads();   // acquires in warp 0 + bar order all threads' h reads
    }
}

// ---------------- launcher ----------------
extern "C" void kernel_launch(void* const* d_in, const int* in_sizes, int n_in,
                              void* d_out, int out_size) {
    (void)in_sizes; (void)n_in; (void)out_size;
    Params P;
    // metadata order: embeds, W_ix, W_ih, b_i, W_fx, W_fh, b_f, W_gx, W_gh, b_g, W_ox, W_oh, b_o
    const float* embeds = (const float*)d_in[0];
    P.Wx[0] = (const float*)d_in[1];  P.Wh[0] = (const float*)d_in[2];  P.b[0] = (const float*)d_in[3];
    P.Wx[1] = (const float*)d_in[4];  P.Wh[1] = (const float*)d_in[5];  P.b[1] = (const float*)d_in[6];
    P.Wx[2] = (const float*)d_in[7];  P.Wh[2] = (const float*)d_in[8];  P.b[2] = (const float*)d_in[9];
    P.Wx[3] = (const float*)d_in[10]; P.Wh[3] = (const float*)d_in[11]; P.b[3] = (const float*)d_in[12];
    P.out = (float*)d_out;

    cudaFuncSetAttribute(lstm_kernel, cudaFuncAttributeMaxDynamicSharedMemorySize, SMEM_TOTAL);

    setup_kernel<<<1, NTHREADS>>>();
    convX_kernel<<<(TSTEPS * NBATCH * EMB) / 4 / NTHREADS, NTHREADS>>>(embeds);
    lstm_kernel<<<CTAS, NTHREADS, SMEM_TOTAL>>>(P);
}

// round 12
// speedup vs baseline: 1.9241x; 1.0326x over previous
#include <cuda_runtime.h>
#include <cuda_fp16.h>
#include <math.h>

#define CTAS     128
#define NTHREADS 256
#define TSTEPS   512
#define NBATCH   64
#define HID      1024
#define EMB      512
#define BROWS    32        // batch rows per CTA  (batch split = 2)
#define NC       16        // cols per gate per CTA (hid split = 64)

// ---------------- device scratch (static, no allocation) ----------------
__device__ __half g_X16[(size_t)TSTEPS * NBATCH * EMB];             // 32 MB
__device__ __half g_xproj[(size_t)TSTEPS * CTAS * BROWS * 64];      // 256 MB
__device__ __half g_hbuf[2][NBATCH * HID];                          // double-buffered h
__device__ unsigned g_arrive[CTAS * 32];                            // padded: 1 flag per 128B line

struct Params {
    const float* Wx[4];   // i,f,g,o : [EMB][HID]
    const float* Wh[4];   // i,f,g,o : [HID][HID]
    const float* b[4];    // i,f,g,o : [HID]
    float* out;           // [T][B][HID]
};

// ---------------- smem layout (bytes) ----------------
// Phase B:
#define OFF_WF     0                       // Wh B-frags: 4 gates x 2 colgrp x 64 ks x 32 lanes x 8B
#define SZ_WF      131072
#define OFF_GATES  (OFF_WF + SZ_WF)        // [32][66] fp32
#define SZ_GATES   (32 * 66 * 4)
#define OFF_XP     (OFF_GATES + SZ_GATES)  // [32][64] fp16
#define SZ_XP      4096
#define OFF_ABUF   (OFF_XP + SZ_XP + 128)  // A tile: 32 rows x 1032 halves
#define SZ_ABUF    (32 * 1032 * 2)
#define SMEM_TOTAL (OFF_ABUF + SZ_ABUF)    // ~209.8 KB
#define A_STRIDE   1032                    // 2064 B/row, == 16 mod 128 -> conflict-free ldmatrix

// Phase A overlay:
#define OFFA_GATES 65536                   // Wx frags occupy [0, 65536)
#define OFFA_BUF0  73984                   // 32 x 520 halves
#define OFFA_BUF1  (73984 + 33280)
#define A_STRIDE_A 520

// ---------------- PTX helpers ----------------
__device__ __forceinline__ unsigned su32(const void* p) {
    return (unsigned)__cvta_generic_to_shared(p);
}
__device__ __forceinline__ void cp16(unsigned s, const void* g) {
    asm volatile("cp.async.cg.shared.global [%0], [%1], 16;\n" :: "r"(s), "l"(g));
}
__device__ __forceinline__ void cp_commit() { asm volatile("cp.async.commit_group;\n"); }
template<int N> __device__ __forceinline__ void cp_wait() {
    asm volatile("cp.async.wait_group %0;\n" :: "n"(N));
}
__device__ __forceinline__ void ldmx4(unsigned r[4], unsigned addr) {
    asm volatile("ldmatrix.sync.aligned.m8n8.x4.shared.b16 {%0,%1,%2,%3}, [%4];\n"
                 : "=r"(r[0]), "=r"(r[1]), "=r"(r[2]), "=r"(r[3]) : "r"(addr));
}
__device__ __forceinline__ void hmma(float acc[4], const unsigned a[4], unsigned b0, unsigned b1) {
    asm volatile("mma.sync.aligned.m16n8k16.row.col.f32.f16.f16.f32 "
                 "{%0,%1,%2,%3},{%4,%5,%6,%7},{%8,%9},{%0,%1,%2,%3};\n"
                 : "+f"(acc[0]), "+f"(acc[1]), "+f"(acc[2]), "+f"(acc[3])
                 : "r"(a[0]), "r"(a[1]), "r"(a[2]), "r"(a[3]), "r"(b0), "r"(b1));
}
// Fast activations (MUFU.EX2 + RCP; rel err ~1e-6, safe at 1e-3 budget)
__device__ __forceinline__ float sigf(float x) {
    return __fdividef(1.0f, 1.0f + __expf(-x));
}
__device__ __forceinline__ float tanhf_fast(float x) {
    return __fdividef(2.0f, 1.0f + __expf(-2.0f * x)) - 1.0f;
}

__device__ __forceinline__ unsigned ld_acq(const unsigned* p) {
    unsigned v;
    asm volatile("ld.acquire.gpu.u32 %0, [%1];" : "=r"(v) : "l"(p));
    return v;
}
__device__ __forceinline__ void st_rel(unsigned* p, unsigned v) {
    asm volatile("st.release.gpu.u32 [%0], %1;" :: "l"(p), "r"(v));
}

// Pre-pack W[k][n] into per-lane mma B-fragments (fp16) in SMEM.
// Unit u = g*2+cg (gate g, col-group cg of 8 cols). Entry index: ((u*nk)+ks)*32 + L.
__device__ void prep_frags(uint2* dst, int nk, const float* const W[4], int hid0, int tid) {
    int total = 8 * nk * 32;
    for (int e = tid; e < total; e += NTHREADS) {
        int L  = e & 31;
        int ks = (e >> 5) % nk;
        int u  = e / (nk * 32);
        int g  = u >> 1, cg = u & 1;
        int t4 = L & 3, gid = L >> 2;
        const float* Wg = W[g];
        int k0 = ks * 16 + 2 * t4;
        int n  = hid0 + cg * 8 + gid;
        __half2 lo = __floats2half2_rn(Wg[(k0    ) * HID + n], Wg[(k0 + 1) * HID + n]);
        __half2 hi = __floats2half2_rn(Wg[(k0 + 8) * HID + n], Wg[(k0 + 9) * HID + n]);
        unsigned ulo = *reinterpret_cast<unsigned*>(&lo);
        unsigned uhi = *reinterpret_cast<unsigned*>(&hi);
        dst[e] = make_uint2(ulo, uhi);
    }
}

// Run CNT k-steps of mma for this warp's 2 col-group tiles (one gate).
template<int CNT>
__device__ __forceinline__ void mma_run(float acc[2][4], unsigned a_lane,
                                        const uint2* b0p, const uint2* b1p, int ks0) {
#pragma unroll
    for (int i = 0; i < CNT; i++) {
        int ks = ks0 + i;
        unsigned a[4];
        ldmx4(a, a_lane + (unsigned)ks * 32u);   // 16 halves = 32 B per kstep
        uint2 q0 = b0p[ks * 32];
        uint2 q1 = b1p[ks * 32];
        hmma(acc[0], a, q0.x, q0.y);
        hmma(acc[1], a, q1.x, q1.y);
    }
}

// ---------------- setup / convert kernels ----------------
__global__ void setup_kernel() {
    int tid = threadIdx.x;
    for (int i = tid; i < CTAS * 32; i += NTHREADS) g_arrive[i] = 0;
    uint4* p = reinterpret_cast<uint4*>(g_hbuf);
    for (int i = tid; i < (2 * NBATCH * HID * 2) / 16; i += NTHREADS)
        p[i] = make_uint4(0, 0, 0, 0);
}

__global__ void convX_kernel(const float* __restrict__ in) {
    int i = blockIdx.x * blockDim.x + threadIdx.x;   // handles 4 floats
    float4 v = reinterpret_cast<const float4*>(in)[i];
    __half2 a = __floats2half2_rn(v.x, v.y);
    __half2 b = __floats2half2_rn(v.z, v.w);
    reinterpret_cast<uint2*>(g_X16)[i] =
        make_uint2(*reinterpret_cast<unsigned*>(&a), *reinterpret_cast<unsigned*>(&b));
}

// ---------------- persistent LSTM kernel ----------------
__global__ void __launch_bounds__(NTHREADS, 1) lstm_kernel(Params P) {
    extern __shared__ char smem[];
    uint2* wfrag   = reinterpret_cast<uint2*>(smem + OFF_WF);
    float* gatesB  = reinterpret_cast<float*>(smem + OFF_GATES);
    __half* xp     = reinterpret_cast<__half*>(smem + OFF_XP);
    float* gatesA  = reinterpret_cast<float*>(smem + OFFA_GATES);

    const int cta  = blockIdx.x;
    const int tid  = threadIdx.x;
    const int w    = tid >> 5;
    const int L    = tid & 31;
    const int hid0 = (cta >> 1) * NC;     // 16 cols/gate
    const int b0   = (cta & 1) * BROWS;   // 32 batch rows

    const unsigned smem_u32 = su32(smem);
    const unsigned abufB_u32 = smem_u32 + OFF_ABUF;
    const unsigned xp_u32    = smem_u32 + OFF_XP;

    // warp tiling: m-tile = w&1 (16 rows), gate = w>>1
    const int m0 = (w & 1) * 16;
    const int wg = w >> 1;                // gate 0..3
    const unsigned lane_off = (unsigned)(m0 + ((L >> 3) & 1) * 8 + (L & 7));
    const unsigned lane_col = (unsigned)((L >> 4) * 8);
    const unsigned a_laneB  = abufB_u32 + (lane_off * A_STRIDE   + lane_col) * 2;
    const unsigned a_laneA0 = smem_u32 + OFFA_BUF0 + (lane_off * A_STRIDE_A + lane_col) * 2;
    const unsigned a_laneA1 = smem_u32 + OFFA_BUF1 + (lane_off * A_STRIDE_A + lane_col) * 2;

    // Phase A epilogue mapping
    const int a_row = tid >> 3, a_cg = tid & 7;

    float breg[8];
    {
        const float* bp = P.b[a_cg >> 1];
#pragma unroll
        for (int i = 0; i < 8; i++) breg[i] = bp[hid0 + (a_cg & 1) * 8 + i];
    }

    // ================= PHASE A: input projection (double-buffered) =================
    prep_frags(wfrag, 32, P.Wx, hid0, tid);
    __syncthreads();

    const uint2* xb0 = wfrag + (size_t)(wg * 2    ) * 32 * 32 + L;
    const uint2* xb1 = wfrag + (size_t)(wg * 2 + 1) * 32 * 32 + L;

    auto loadA = [&](int t, int buf) {
        unsigned base = smem_u32 + (buf ? OFFA_BUF1 : OFFA_BUF0);
#pragma unroll
        for (int jj = 0; jj < 8; jj++) {
            int c = tid + jj * NTHREADS;
            int row = c >> 6, col = c & 63;
            cp16(base + row * (A_STRIDE_A * 2) + col * 16,
                 (const char*)g_X16 + ((size_t)(t * NBATCH + b0 + row) * EMB) * 2 + col * 16);
        }
        cp_commit();
    };

    loadA(0, 0);
    for (int t = 0; t < TSTEPS; t++) {
        if (t + 1 < TSTEPS) { loadA(t + 1, (t + 1) & 1); cp_wait<1>(); }
        else                { cp_wait<0>(); }
        __syncthreads();

        float acc[2][4] = {{0,0,0,0},{0,0,0,0}};
        mma_run<32>(acc, (t & 1) ? a_laneA1 : a_laneA0, xb0, xb1, 0);

        {
            int gid = L >> 2, t4 = L & 3;
#pragma unroll
            for (int s = 0; s < 2; s++) {
                int colb = wg * 16 + s * 8 + 2 * t4;
                *reinterpret_cast<float2*>(&gatesA[(m0 + gid    ) * 66 + colb]) = make_float2(acc[s][0], acc[s][1]);
                *reinterpret_cast<float2*>(&gatesA[(m0 + gid + 8) * 66 + colb]) = make_float2(acc[s][2], acc[s][3]);
            }
        }
        __syncthreads();

        {
            float v[8];
#pragma unroll
            for (int i = 0; i < 8; i++)
                v[i] = gatesA[a_row * 66 + a_cg * 8 + i] + breg[i];
            __half2 h0 = __floats2half2_rn(v[0], v[1]);
            __half2 h1 = __floats2half2_rn(v[2], v[3]);
            __half2 h2 = __floats2half2_rn(v[4], v[5]);
            __half2 h3 = __floats2half2_rn(v[6], v[7]);
            uint4 pk = make_uint4(*reinterpret_cast<unsigned*>(&h0), *reinterpret_cast<unsigned*>(&h1),
                                  *reinterpret_cast<unsigned*>(&h2), *reinterpret_cast<unsigned*>(&h3));
            size_t off = (((size_t)t * CTAS + cta) * BROWS + a_row) * 64 + a_cg * 8;
            *reinterpret_cast<uint4*>(&g_xproj[off]) = pk;
        }
    }

    // ================= PHASE B: recurrence (producer-flag staged sync) =================
    __syncthreads();
    prep_frags(wfrag, 64, P.Wh, hid0, tid);
    __syncthreads();

    const uint2* hb0 = wfrag + (size_t)(wg * 2    ) * 64 * 32 + L;
    const uint2* hb1 = wfrag + (size_t)(wg * 2 + 1) * 64 * 32 + L;

    float creg[2] = {0.0f, 0.0f};
    const int e_base = tid * 2;
    const int e_row  = e_base >> 4;       // 0..31
    const int e_j    = e_base & 15;       // even col in 0..15

    // producer flag index for (quarter q, lane l): CTA 2*(16q+l) + (cta&1)
    const int bpar = cta & 1;

    // prologue: prefetch xproj(0)
    cp16(xp_u32 + tid * 16,
         (const char*)&g_xproj[((size_t)0 * CTAS + cta) * BROWS * 64] + tid * 16);
    cp_commit();   // outstanding: {xp}

    for (int t = 0; t < TSTEPS; t++) {
        const __half* hsrc = g_hbuf[t & 1] + (size_t)b0 * HID;

        // load quarter q: 32 rows x 32 chunks (1024 chunks -> 4/thread)
        auto loadQ = [&](int kq) {
#pragma unroll
            for (int jj = 0; jj < 4; jj++) {
                int c = tid + jj * NTHREADS;
                int row = c >> 5;
                int col = (kq << 5) + (c & 31);
                cp16(abufB_u32 + row * (A_STRIDE * 2) + col * 16,
                     (const char*)hsrc + row * (HID * 2) + col * 16);
            }
            cp_commit();
        };
        // poll producers of quarter q (warp 0, lanes 0-15)
        auto pollQ = [&](int kq) {
            if (tid < 16) {
                const unsigned* f = &g_arrive[((16 * kq + tid) * 2 + bpar) * 32];
                while (ld_acq(f) < (unsigned)t) { }
            }
        };

        float acc[2][4] = {{0,0,0,0},{0,0,0,0}};

        pollQ(0);
        __syncthreads();
        loadQ(0);                          // {xp, q0}
        pollQ(1);
        __syncthreads();
        loadQ(1);                          // {xp, q0, q1}

        cp_wait<1>();                      // xp + q0 done
        pollQ(2);
        __syncthreads();
        loadQ(2);                          // {q1, q2}
        mma_run<16>(acc, a_laneB, hb0, hb1, 0);

        cp_wait<1>();                      // q1 done
        pollQ(3);
        __syncthreads();
        loadQ(3);                          // {q2, q3}
        mma_run<16>(acc, a_laneB, hb0, hb1, 16);

        cp_wait<1>(); __syncthreads();     // q2 done
        mma_run<16>(acc, a_laneB, hb0, hb1, 32);

        cp_wait<0>(); __syncthreads();     // q3 done
        mma_run<16>(acc, a_laneB, hb0, hb1, 48);

        // fragments -> gatesB smem
        {
            int gid = L >> 2, t4 = L & 3;
#pragma unroll
            for (int s = 0; s < 2; s++) {
                int colb = wg * 16 + s * 8 + 2 * t4;
                *reinterpret_cast<float2*>(&gatesB[(m0 + gid    ) * 66 + colb]) = make_float2(acc[s][0], acc[s][1]);
                *reinterpret_cast<float2*>(&gatesB[(m0 + gid + 8) * 66 + colb]) = make_float2(acc[s][2], acc[s][3]);
            }
        }
        __syncthreads();

        // elementwise LSTM cell
        __half* hdst = g_hbuf[(t + 1) & 1];
#pragma unroll
        for (int u = 0; u < 2; u++) {
            int jj = e_j + u;
            float zi = gatesB[e_row * 66 +       jj] + __half2float(xp[e_row * 64 +       jj]);
            float zf = gatesB[e_row * 66 + 16 +  jj] + __half2float(xp[e_row * 64 + 16 +  jj]);
            float zg = gatesB[e_row * 66 + 32 +  jj] + __half2float(xp[e_row * 64 + 32 +  jj]);
            float zo = gatesB[e_row * 66 + 48 +  jj] + __half2float(xp[e_row * 64 + 48 +  jj]);
            float it = sigf(zi);
            float ft = sigf(zf);
            float gt = tanhf_fast(zg);
            float ot = sigf(zo);
            float cn = gt * it + creg[u] * ft;
            creg[u] = cn;
            float hn = tanhf_fast(cn) * ot;
            hdst[(b0 + e_row) * HID + hid0 + jj] = __float2half(hn);
            P.out[((size_t)(t * NBATCH + b0 + e_row)) * HID + hid0 + jj] = hn;
        }

        // ---- post my step flag; prefetch xp(t+1) ----
        __syncthreads();                   // all h/out/xp-reads of this CTA complete
        if (tid == 0) st_rel(&g_arrive[cta * 32], (unsigned)(t + 1));
        if (t + 1 < TSTEPS) {
            cp16(xp_u32 + tid * 16,
                 (const char*)&g_xproj[(((size_t)(t + 1) * CTAS + cta) * BROWS) * 64] + tid * 16);
            cp_commit();                   // {xp} outstanding for next step
        }
    }
}

// ---------------- launcher ----------------
extern "C" void kernel_launch(void* const* d_in, const int* in_sizes, int n_in,
                              void* d_out, int out_size) {
    (void)in_sizes; (void)n_in; (void)out_size;
    Params P;
    // metadata order: embeds, W_ix, W_ih, b_i, W_fx, W_fh, b_f, W_gx, W_gh, b_g, W_ox, W_oh, b_o
    const float* embeds = (const float*)d_in[0];
    P.Wx[0] = (const float*)d_in[1];  P.Wh[0] = (const float*)d_in[2];  P.b[0] = (const float*)d_in[3];
    P.Wx[1] = (const float*)d_in[4];  P.Wh[1] = (const float*)d_in[5];  P.b[1] = (const float*)d_in[6];
    P.Wx[2] = (const float*)d_in[7];  P.Wh[2] = (const float*)d_in[8];  P.b[2] = (const float*)d_in[9];
    P.Wx[3] = (const float*)d_in[10]; P.Wh[3] = (const float*)d_in[11]; P.b[3] = (const float*)d_in[12];
    P.out = (float*)d_out;

    cudaFuncSetAttribute(lstm_kernel, cudaFuncAttributeMaxDynamicSharedMemorySize, SMEM_TOTAL);

    setup_kernel<<<1, NTHREADS>>>();
    convX_kernel<<<(TSTEPS * NBATCH * EMB) / 4 / NTHREADS, NTHREADS>>>(embeds);
    lstm_kernel<<<CTAS, NTHREADS, SMEM_TOTAL>>>(P);
}